// round 11
// baseline (speedup 1.0000x reference)
#include <cuda_runtime.h>
#include <math.h>
#include <limits.h>

// Fixed problem shape (setup_inputs): B=8, P=512, Q=4096, H=W=512
#define B_   8
#define P_   512
#define Q_   4096
#define N_   4096
#define R_   45
#define HW_  512

#define THREADS_   256
#define PTS_BLOCKS 256   // 8 warps x 2 queries; 32 blocks per batch
#define CE_BLOCKS  64    // 512 queries per block (2 per thread)
#define TOTAL_BLOCKS (PTS_BLOCKS + CE_BLOCKS)

#define NSTRIPS 16       // 32-px y strips
#define SCAP    128      // capacity per strip (Binomial(512,1/16) mean 32 — cap 128 unreachable)

__device__ float        g_pts_part[PTS_BLOCKS];
__device__ float        g_ce_num[CE_BLOCKS];
__device__ float        g_ce_den[CE_BLOCKS];
__device__ unsigned int g_done;          // 0 at load; final block self-resets

__device__ __forceinline__ float warp_sum(float v) {
    #pragma unroll
    for (int o = 16; o; o >>= 1) v += __shfl_xor_sync(0xffffffffu, v, o);
    return v;
}

// warp-0-only: publish partials, count done blocks, last block reduces everything
__device__ __forceinline__ void tail_w0(int lane, float* out) {
    unsigned last = 0u;
    if (lane == 0) {
        __threadfence();
        last = (atomicAdd(&g_done, 1u) == (unsigned)(TOTAL_BLOCKS - 1)) ? 1u : 0u;
    }
    last = __shfl_sync(0xffffffffu, last, 0);
    if (last) {
        __threadfence();
        volatile float* pp = g_pts_part;
        volatile float* cn = g_ce_num;
        volatile float* cd = g_ce_den;
        float pvs = 0.f;
        #pragma unroll
        for (int i = 0; i < PTS_BLOCKS / 32; i++) pvs += pp[i * 32 + lane];
        float nn = cn[lane] + cn[lane + 32];
        float dd = cd[lane] + cd[lane + 32];
        pvs = warp_sum(pvs);
        nn  = warp_sum(nn);
        dd  = warp_sum(dd);
        if (lane == 0) {
            out[0] = nn / dd + 0.5f * pvs / (float)N_;
            g_done = 0u;                       // reset for graph replay
        }
    }
}

__global__ void __launch_bounds__(THREADS_) k_fused(
    const float* __restrict__ tp,
    const float* __restrict__ sp,
    const float* __restrict__ logits,
    const int*   __restrict__ sidx,
    float* __restrict__ out)
{
    __shared__ int      s_strip[NSTRIPS * SCAP];   // 8KB, strip-binned packed px|py<<16
    __shared__ int      s_cnt[NSTRIPS];
    __shared__ float    sm[8], sm2[8], sm3[8];
    __shared__ unsigned bm[Q_ / 32];               // CE branch bitmap (128 words)

    const int tid  = threadIdx.x;
    const int bid  = blockIdx.x;
    const int warp = tid >> 5, lane = tid & 31;

    if (bid < PTS_BLOCKS) {
        // ===== points focal loss: strip binning (no prefix scan, no scatter pass) =====
        const int b = bid >> 5;                    // 32 blocks per batch

        // independent loads up front
        float4 sq = ((const float4*)sp)[bid * 8 + warp];              // 2 queries/warp
        float4 pv = ((const float4*)(tp + (size_t)b * P_ * 2))[tid];  // 2 points/thread

        // query setup (only depends on sq)
        int   x0[2], y0[2];
        float wx[2], wy[2];
        {
            float qx[2] = { sq.x, sq.z };
            float qy[2] = { sq.y, sq.w };
            #pragma unroll
            for (int j = 0; j < 2; j++) {
                float x = fminf(fmaxf(qx[j] * (float)HW_, 0.f), (float)(HW_ - 1));
                float y = fminf(fmaxf(qy[j] * (float)HW_, 0.f), (float)(HW_ - 1));
                float x0f = floorf(x), y0f = floorf(y);
                x0[j] = (int)x0f; y0[j] = (int)y0f;
                wx[j] = x - x0f;  wy[j] = y - y0f;
            }
        }

        if (tid < NSTRIPS) s_cnt[tid] = 0;
        __syncthreads();                                              // B1

        // bin both points directly (atomic rank + store; no second pass)
        {
            int pxa = min(max((int)rintf(pv.x), 0), HW_ - 1);
            int pya = min(max((int)rintf(pv.y), 0), HW_ - 1);
            int pxb = min(max((int)rintf(pv.z), 0), HW_ - 1);
            int pyb = min(max((int)rintf(pv.w), 0), HW_ - 1);
            int sA = pya >> 5, sB = pyb >> 5;
            int rA = atomicAdd(&s_cnt[sA], 1);
            int rB = atomicAdd(&s_cnt[sB], 1);
            s_strip[sA * SCAP + rA] = pxa | (pya << 16);
            s_strip[sB * SCAP + rB] = pxb | (pyb << 16);
        }
        __syncthreads();                                              // B2

        // scan: 2 queries, strips covering [y0-45, y0+46]
        int m[2][4];
        #pragma unroll
        for (int j = 0; j < 2; j++)
            #pragma unroll
            for (int cc = 0; cc < 4; cc++) m[j][cc] = INT_MAX;

        #pragma unroll
        for (int j = 0; j < 2; j++) {
            int slo = max(y0[j] - R_, 0) >> 5;
            int shi = min(y0[j] + R_ + 1, HW_ - 1) >> 5;
            for (int st = slo; st <= shi; st++) {
                int cnt = s_cnt[st];
                const int* base = s_strip + st * SCAP;
                for (int t = lane; t < cnt; t += 32) {
                    int w  = base[t];
                    int px = w & 0xFFFF, py = w >> 16;
                    int dx0 = x0[j] - px, dy0 = y0[j] - py;
                    bool cx0 = (unsigned)(dx0 + R_)     <= 2u * R_;
                    bool cx1 = (unsigned)(dx0 + R_ + 1) <= 2u * R_;
                    bool cy0 = (unsigned)(dy0 + R_)     <= 2u * R_;
                    bool cy1 = (unsigned)(dy0 + R_ + 1) <= 2u * R_;
                    int k00 = dx0 * dx0 + dy0 * dy0;
                    int k01 = k00 + 2 * dx0 + 1;
                    int k10 = k00 + 2 * dy0 + 1;
                    int k11 = k01 + 2 * dy0 + 1;
                    if (cx0 && cy0) m[j][0] = min(m[j][0], k00);
                    if (cx1 && cy0) m[j][1] = min(m[j][1], k01);
                    if (cx0 && cy1) m[j][2] = min(m[j][2], k10);
                    if (cx1 && cy1) m[j][3] = min(m[j][3], k11);
                }
            }
        }
        #pragma unroll
        for (int j = 0; j < 2; j++)
            #pragma unroll
            for (int cc = 0; cc < 4; cc++)
                m[j][cc] = (int)__reduce_min_sync(0xffffffffu, (unsigned)m[j][cc]);

        // lane-parallel epilogue: lane 4j+c -> query j, corner c (lanes 0-7)
        {
            int jj = (lane >> 2) & 1, cc = lane & 3;
            int mv = (jj == 0)
                ? ((cc == 0) ? m[0][0] : (cc == 1) ? m[0][1] : (cc == 2) ? m[0][2] : m[0][3])
                : ((cc == 0) ? m[1][0] : (cc == 1) ? m[1][1] : (cc == 2) ? m[1][2] : m[1][3]);
            float wxs = jj ? wx[1] : wx[0];
            float wys = jj ? wy[1] : wy[0];
            float fwx = (cc & 1) ? wxs : 1.f - wxs;
            float fwy = (cc & 2) ? wys : 1.f - wys;

            const float inv = 1.0f / (2.0f * 15.0f * 15.0f);
            float v = __expf(-(float)mv * inv);           // INT_MAX underflows to 0
            float term = v * fwx * fwy;
            term += __shfl_xor_sync(0xffffffffu, term, 1);
            term += __shfl_xor_sync(0xffffffffu, term, 2); // p_j per 4-lane group
            float om  = 1.f - term;
            float raw = -om * om * __logf(fmaxf(term, 1e-6f));
            raw += __shfl_xor_sync(0xffffffffu, raw, 4);   // q0 + q1 at lane 0
            if (lane == 0) sm[warp] = raw;
        }
        __syncthreads();                                              // B3
        if (warp == 0) {
            float v = (lane < 8) ? sm[lane] : 0.f;
            v = warp_sum(v);
            if (lane == 0) g_pts_part[bid] = v;
            tail_w0(lane, out);
        }
    } else {
        // ====== CE: weighted cross-entropy, one block per 512-query slice ======
        const int cb = bid - PTS_BLOCKS;
        const int b  = cb >> 3;
        const int s  = cb & 7;

        float4 l = ((const float4*)(logits + (size_t)b * Q_ * 2 + s * 1024))[tid];
        int i0 = sidx[b * P_ + tid];
        int i1 = sidx[b * P_ + 256 + tid];

        if (tid < Q_ / 32) bm[tid] = 0u;
        __syncthreads();                                              // B1
        atomicOr(&bm[i0 >> 5], 1u << (i0 & 31));
        atomicOr(&bm[i1 >> 5], 1u << (i1 & 31));
        __syncthreads();                                              // B2

        int q0 = s * 512 + 2 * tid, q1 = q0 + 1;
        bool f0 = (bm[q0 >> 5] >> (q0 & 31)) & 1u;
        bool f1 = (bm[q1 >> 5] >> (q1 & 31)) & 1u;
        float d0 = l.y - l.x, d1 = l.w - l.z;
        // softplus(-d) = softplus(d) - d
        float sp0 = fmaxf(d0, 0.f) + __logf(1.f + __expf(-fabsf(d0)));
        float sp1 = fmaxf(d1, 0.f) + __logf(1.f + __expf(-fabsf(d1)));
        float num = (f0 ? sp0 - d0 : 0.5f * sp0)
                  + (f1 ? sp1 - d1 : 0.5f * sp1);
        float den = (f0 ? 1.f : 0.5f) + (f1 ? 1.f : 0.5f);

        num = warp_sum(num);
        den = warp_sum(den);
        if (lane == 0) { sm2[warp] = num; sm3[warp] = den; }
        __syncthreads();                                              // B3
        if (warp == 0) {
            float n = (lane < 8) ? sm2[lane] : 0.f;
            float d = (lane < 8) ? sm3[lane] : 0.f;
            n = warp_sum(n);
            d = warp_sum(d);
            if (lane == 0) { g_ce_num[cb] = n; g_ce_den[cb] = d; }
            tail_w0(lane, out);
        }
    }
}

extern "C" void kernel_launch(void* const* d_in, const int* in_sizes, int n_in,
                              void* d_out, int out_size) {
    const float* tp     = (const float*)d_in[0];
    const float* sp     = (const float*)d_in[1];
    const float* logits = (const float*)d_in[2];
    const int*   sidx   = (const int*)  d_in[4];

    k_fused<<<TOTAL_BLOCKS, THREADS_>>>(tp, sp, logits, sidx, (float*)d_out);
}

// round 12
// speedup vs baseline: 1.1286x; 1.1286x over previous
#include <cuda_runtime.h>
#include <math.h>
#include <limits.h>

// Fixed problem shape (setup_inputs): B=8, P=512, Q=4096, H=W=512
#define B_   8
#define P_   512
#define Q_   4096
#define N_   4096
#define R_   45
#define HW_  512

#define THREADS_   256
#define PTS_BLOCKS 256   // 8 warps/block x 2 queries/warp; 32 blocks per batch
#define CE_BLOCKS  64    // 512 queries per block (2 per thread)
#define TOTAL_BLOCKS (PTS_BLOCKS + CE_BLOCKS)

__device__ float        g_pts_part[PTS_BLOCKS];
__device__ float        g_ce_num[CE_BLOCKS];
__device__ float        g_ce_den[CE_BLOCKS];
__device__ unsigned int g_done;          // 0 at load; final block self-resets

__device__ __forceinline__ float warp_sum(float v) {
    #pragma unroll
    for (int o = 16; o; o >>= 1) v += __shfl_xor_sync(0xffffffffu, v, o);
    return v;
}

// release-scoped done-counter increment: fence folded into the atomic
__device__ __forceinline__ unsigned done_inc_release() {
    unsigned old;
    asm volatile("atom.add.release.gpu.u32 %0, [%1], 1;"
                 : "=r"(old) : "l"(&g_done) : "memory");
    return old;
}

__device__ __forceinline__ void st_cg(float* p, float v) {
    asm volatile("st.global.cg.f32 [%0], %1;" :: "l"(p), "f"(v) : "memory");
}

__global__ void __launch_bounds__(THREADS_) k_fused(
    const float* __restrict__ tp,
    const float* __restrict__ sp,
    const float* __restrict__ logits,
    const int*   __restrict__ sidx,
    float* __restrict__ out)
{
    __shared__ int      s_pts[P_];        // cell-sorted, packed px | py<<16
    __shared__ int      s_cnt[64];
    __shared__ int      s_off[65];
    __shared__ float    sm[8], sm2[8], sm3[8];
    __shared__ unsigned bm[Q_ / 32];      // 128 words (CE branch)
    __shared__ int      s_last;

    const int tid  = threadIdx.x;
    const int bid  = blockIdx.x;
    const int warp = tid >> 5, lane = tid & 31;

    if (bid < PTS_BLOCKS) {
        // ===== points focal loss: 2D counting sort + 2 queries per warp =====
        const int b = bid >> 5;                       // 32 blocks per batch
        const int qbase = bid * 16 + warp * 2;

        float4 sq = ((const float4*)sp)[qbase >> 1];
        float qx[2] = { sq.x, sq.z };
        float qy[2] = { sq.y, sq.w };
        int   x0[2], y0[2];
        float wx[2], wy[2];
        #pragma unroll
        for (int j = 0; j < 2; j++) {
            float x = fminf(fmaxf(qx[j] * (float)HW_, 0.f), (float)(HW_ - 1));
            float y = fminf(fmaxf(qy[j] * (float)HW_, 0.f), (float)(HW_ - 1));
            float x0f = floorf(x), y0f = floorf(y);
            x0[j] = (int)x0f; y0[j] = (int)y0f;
            wx[j] = x - x0f;  wy[j] = y - y0f;
        }

        if (tid < 64) s_cnt[tid] = 0;
        __syncthreads();

        int pkA, pkB, cA, cB, rA, rB;
        {
            float4 v = ((const float4*)(tp + (size_t)b * P_ * 2))[tid];
            int pxa = min(max((int)rintf(v.x), 0), HW_ - 1);
            int pya = min(max((int)rintf(v.y), 0), HW_ - 1);
            int pxb = min(max((int)rintf(v.z), 0), HW_ - 1);
            int pyb = min(max((int)rintf(v.w), 0), HW_ - 1);
            pkA = pxa | (pya << 16);  cA = ((pya >> 6) << 3) | (pxa >> 6);
            pkB = pxb | (pyb << 16);  cB = ((pyb >> 6) << 3) | (pxb >> 6);
            rA = atomicAdd(&s_cnt[cA], 1);
            rB = atomicAdd(&s_cnt[cB], 1);
        }
        __syncthreads();
        if (warp == 0) {                              // 64-cell exclusive scan
            int i0 = s_cnt[lane], i1 = s_cnt[lane + 32];
            #pragma unroll
            for (int o = 1; o < 32; o <<= 1) {
                int t = __shfl_up_sync(0xffffffffu, i0, o); if (lane >= o) i0 += t;
                int u = __shfl_up_sync(0xffffffffu, i1, o); if (lane >= o) i1 += u;
            }
            i1 += __shfl_sync(0xffffffffu, i0, 31);
            s_off[lane + 1]  = i0;
            s_off[lane + 33] = i1;
            if (lane == 0) s_off[0] = 0;
        }
        __syncthreads();
        s_pts[s_off[cA] + rA] = pkA;
        s_pts[s_off[cB] + rB] = pkB;
        __syncthreads();

        int m[2][4];
        #pragma unroll
        for (int j = 0; j < 2; j++)
            #pragma unroll
            for (int cc = 0; cc < 4; cc++) m[j][cc] = INT_MAX;

        #pragma unroll
        for (int j = 0; j < 2; j++) {
            int cxlo = max(x0[j] - R_, 0) >> 6;
            int cxhi = min(x0[j] + R_ + 1, HW_ - 1) >> 6;
            int cylo = max(y0[j] - R_, 0) >> 6;
            int cyhi = min(y0[j] + R_ + 1, HW_ - 1) >> 6;
            for (int cy = cylo; cy <= cyhi; cy++) {
                int j0 = s_off[(cy << 3) | cxlo];
                int j1 = s_off[(cy << 3) + cxhi + 1];
                for (int t = j0 + lane; t < j1; t += 32) {
                    int w  = s_pts[t];
                    int px = w & 0xFFFF, py = w >> 16;
                    int dx0 = x0[j] - px, dy0 = y0[j] - py;
                    bool cx0 = (unsigned)(dx0 + R_)     <= 2u * R_;
                    bool cx1 = (unsigned)(dx0 + R_ + 1) <= 2u * R_;
                    bool cy0 = (unsigned)(dy0 + R_)     <= 2u * R_;
                    bool cy1 = (unsigned)(dy0 + R_ + 1) <= 2u * R_;
                    int k00 = dx0 * dx0 + dy0 * dy0;
                    int k01 = k00 + 2 * dx0 + 1;
                    int k10 = k00 + 2 * dy0 + 1;
                    int k11 = k01 + 2 * dy0 + 1;
                    if (cx0 && cy0) m[j][0] = min(m[j][0], k00);
                    if (cx1 && cy0) m[j][1] = min(m[j][1], k01);
                    if (cx0 && cy1) m[j][2] = min(m[j][2], k10);
                    if (cx1 && cy1) m[j][3] = min(m[j][3], k11);
                }
            }
        }
        #pragma unroll
        for (int j = 0; j < 2; j++)
            #pragma unroll
            for (int cc = 0; cc < 4; cc++)
                m[j][cc] = (int)__reduce_min_sync(0xffffffffu, (unsigned)m[j][cc]);

        // lane-parallel epilogue: lane 4j+c -> query j, corner c (lanes 0-7)
        {
            int jj = (lane >> 2) & 1, cc = lane & 3;
            int mv = (jj == 0)
                ? ((cc == 0) ? m[0][0] : (cc == 1) ? m[0][1] : (cc == 2) ? m[0][2] : m[0][3])
                : ((cc == 0) ? m[1][0] : (cc == 1) ? m[1][1] : (cc == 2) ? m[1][2] : m[1][3]);
            float wxs = jj ? wx[1] : wx[0];
            float wys = jj ? wy[1] : wy[0];
            float fwx = (cc & 1) ? wxs : 1.f - wxs;
            float fwy = (cc & 2) ? wys : 1.f - wys;

            const float inv = 1.0f / (2.0f * 15.0f * 15.0f);
            float v = __expf(-(float)mv * inv);       // INT_MAX underflows to 0
            float term = v * fwx * fwy;
            term += __shfl_xor_sync(0xffffffffu, term, 1);
            term += __shfl_xor_sync(0xffffffffu, term, 2);
            float om  = 1.f - term;
            float raw = -om * om * __logf(fmaxf(term, 1e-6f));
            raw += __shfl_xor_sync(0xffffffffu, raw, 4);
            if (lane == 0) sm[warp] = raw;
        }
        __syncthreads();
        if (warp == 0) {
            float v = (lane < 8) ? sm[lane] : 0.f;
            v = warp_sum(v);
            if (lane == 0) st_cg(&g_pts_part[bid], v);
        }
    } else {
        // ====== CE: weighted cross-entropy, one block per 512-query slice ======
        const int cb = bid - PTS_BLOCKS;
        const int b  = cb >> 3;
        const int s  = cb & 7;

        float4 l = ((const float4*)(logits + (size_t)b * Q_ * 2 + s * 1024))[tid];
        int i0 = sidx[b * P_ + tid];
        int i1 = sidx[b * P_ + 256 + tid];

        if (tid < Q_ / 32) bm[tid] = 0u;
        __syncthreads();
        atomicOr(&bm[i0 >> 5], 1u << (i0 & 31));
        atomicOr(&bm[i1 >> 5], 1u << (i1 & 31));
        __syncthreads();

        int q0 = s * 512 + 2 * tid, q1 = q0 + 1;
        bool f0 = (bm[q0 >> 5] >> (q0 & 31)) & 1u;
        bool f1 = (bm[q1 >> 5] >> (q1 & 31)) & 1u;
        float d0 = l.y - l.x, d1 = l.w - l.z;
        float sp0 = fmaxf(d0, 0.f) + __logf(1.f + __expf(-fabsf(d0)));
        float sp1 = fmaxf(d1, 0.f) + __logf(1.f + __expf(-fabsf(d1)));
        float num = (f0 ? sp0 - d0 : 0.5f * sp0)
                  + (f1 ? sp1 - d1 : 0.5f * sp1);
        float den = (f0 ? 1.f : 0.5f) + (f1 ? 1.f : 0.5f);

        num = warp_sum(num);
        den = warp_sum(den);
        if (lane == 0) { sm2[warp] = num; sm3[warp] = den; }
        __syncthreads();
        if (warp == 0) {
            float n = (lane < 8) ? sm2[lane] : 0.f;
            float d = (lane < 8) ? sm3[lane] : 0.f;
            n = warp_sum(n);
            d = warp_sum(d);
            if (lane == 0) {
                st_cg(&g_ce_num[cb], n);
                st_cg(&g_ce_den[cb], d);
            }
        }
    }

    // ---------------- last-block-done finalize (release atomic, no MEMBAR/block) ----------------
    __syncthreads();
    if (tid == 0)
        s_last = (done_inc_release() == (unsigned)(TOTAL_BLOCKS - 1)) ? 1 : 0;
    __syncthreads();
    if (s_last) {
        __threadfence();                       // acquire side (final block only)
        volatile float* pp = g_pts_part;
        volatile float* cn = g_ce_num;
        volatile float* cd = g_ce_den;

        float v = (tid < PTS_BLOCKS) ? pp[tid] : 0.f;
        float n = (tid < CE_BLOCKS)  ? cn[tid] : 0.f;
        float d = (tid < CE_BLOCKS)  ? cd[tid] : 0.f;
        v = warp_sum(v);
        n = warp_sum(n);
        d = warp_sum(d);
        if (lane == 0) { sm[warp] = v; sm2[warp] = n; sm3[warp] = d; }
        __syncthreads();
        if (tid == 0) {
            float pvs = 0.f, nn = 0.f, dd = 0.f;
            #pragma unroll
            for (int k = 0; k < 8; k++) { pvs += sm[k]; nn += sm2[k]; dd += sm3[k]; }
            out[0] = nn / dd + 0.5f * pvs / (float)N_;
            g_done = 0u;                       // reset for graph replay
        }
    }
}

extern "C" void kernel_launch(void* const* d_in, const int* in_sizes, int n_in,
                              void* d_out, int out_size) {
    const float* tp     = (const float*)d_in[0];
    const float* sp     = (const float*)d_in[1];
    const float* logits = (const float*)d_in[2];
    const int*   sidx   = (const int*)  d_in[4];

    k_fused<<<TOTAL_BLOCKS, THREADS_>>>(tp, sp, logits, sidx, (float*)d_out);
}

// round 13
// speedup vs baseline: 1.1326x; 1.0036x over previous
#include <cuda_runtime.h>
#include <math.h>
#include <limits.h>

// Fixed problem shape (setup_inputs): B=8, P=512, Q=4096, H=W=512
#define B_   8
#define P_   512
#define Q_   4096
#define N_   4096
#define R_   45
#define HW_  512

#define THREADS_   256
#define PTS_BLOCKS 256   // 8 warps/block x 2 queries/warp; 32 blocks per batch
#define CE_BLOCKS  64    // 512 queries per block (2 per thread)
#define TOTAL_BLOCKS (PTS_BLOCKS + CE_BLOCKS)

#define FXS 268435456.0f   // 2^28 fixed-point scale (exact integer adds => deterministic)

__device__ unsigned long long g_acc_pts;   // sum(raw) * 2^28
__device__ unsigned long long g_acc_num;   // CE numerator * 2^28
__device__ unsigned long long g_acc_k;     // count of flagged (b,q)
__device__ unsigned int       g_done;      // 0 at load; final block self-resets

__device__ __forceinline__ float warp_sum(float v) {
    #pragma unroll
    for (int o = 16; o; o >>= 1) v += __shfl_xor_sync(0xffffffffu, v, o);
    return v;
}

__global__ void __launch_bounds__(THREADS_) k_fused(
    const float* __restrict__ tp,
    const float* __restrict__ sp,
    const float* __restrict__ logits,
    const int*   __restrict__ sidx,
    float* __restrict__ out)
{
    __shared__ int      s_pts[P_];        // cell-sorted, packed px | py<<16
    __shared__ int      s_cnt[64];
    __shared__ int      s_off[65];
    __shared__ float    sm[8], sm2[8];
    __shared__ int      smi[8];
    __shared__ unsigned bm[Q_ / 32];      // 128 words (CE branch)
    __shared__ int      s_last;

    const int tid  = threadIdx.x;
    const int bid  = blockIdx.x;
    const int warp = tid >> 5, lane = tid & 31;

    if (bid < PTS_BLOCKS) {
        // ===== points focal loss: 2D counting sort + 2 queries per warp =====
        const int b = bid >> 5;                       // 32 blocks per batch
        const int qbase = bid * 16 + warp * 2;

        float4 sq = ((const float4*)sp)[qbase >> 1];
        float qx[2] = { sq.x, sq.z };
        float qy[2] = { sq.y, sq.w };
        int   x0[2], y0[2];
        float wx[2], wy[2];
        #pragma unroll
        for (int j = 0; j < 2; j++) {
            float x = fminf(fmaxf(qx[j] * (float)HW_, 0.f), (float)(HW_ - 1));
            float y = fminf(fmaxf(qy[j] * (float)HW_, 0.f), (float)(HW_ - 1));
            float x0f = floorf(x), y0f = floorf(y);
            x0[j] = (int)x0f; y0[j] = (int)y0f;
            wx[j] = x - x0f;  wy[j] = y - y0f;
        }

        if (tid < 64) s_cnt[tid] = 0;
        __syncthreads();

        int pkA, pkB, cA, cB, rA, rB;
        {
            float4 v = ((const float4*)(tp + (size_t)b * P_ * 2))[tid];
            int pxa = min(max((int)rintf(v.x), 0), HW_ - 1);
            int pya = min(max((int)rintf(v.y), 0), HW_ - 1);
            int pxb = min(max((int)rintf(v.z), 0), HW_ - 1);
            int pyb = min(max((int)rintf(v.w), 0), HW_ - 1);
            pkA = pxa | (pya << 16);  cA = ((pya >> 6) << 3) | (pxa >> 6);
            pkB = pxb | (pyb << 16);  cB = ((pyb >> 6) << 3) | (pxb >> 6);
            rA = atomicAdd(&s_cnt[cA], 1);
            rB = atomicAdd(&s_cnt[cB], 1);
        }
        __syncthreads();
        if (warp == 0) {                              // 64-cell exclusive scan
            int i0 = s_cnt[lane], i1 = s_cnt[lane + 32];
            #pragma unroll
            for (int o = 1; o < 32; o <<= 1) {
                int t = __shfl_up_sync(0xffffffffu, i0, o); if (lane >= o) i0 += t;
                int u = __shfl_up_sync(0xffffffffu, i1, o); if (lane >= o) i1 += u;
            }
            i1 += __shfl_sync(0xffffffffu, i0, 31);
            s_off[lane + 1]  = i0;
            s_off[lane + 33] = i1;
            if (lane == 0) s_off[0] = 0;
        }
        __syncthreads();
        s_pts[s_off[cA] + rA] = pkA;
        s_pts[s_off[cB] + rB] = pkB;
        __syncthreads();

        int m[2][4];
        #pragma unroll
        for (int j = 0; j < 2; j++)
            #pragma unroll
            for (int cc = 0; cc < 4; cc++) m[j][cc] = INT_MAX;

        #pragma unroll
        for (int j = 0; j < 2; j++) {
            int cxlo = max(x0[j] - R_, 0) >> 6;
            int cxhi = min(x0[j] + R_ + 1, HW_ - 1) >> 6;
            int cylo = max(y0[j] - R_, 0) >> 6;
            int cyhi = min(y0[j] + R_ + 1, HW_ - 1) >> 6;
            for (int cy = cylo; cy <= cyhi; cy++) {
                int j0 = s_off[(cy << 3) | cxlo];
                int j1 = s_off[(cy << 3) + cxhi + 1];
                for (int t = j0 + lane; t < j1; t += 32) {
                    int w  = s_pts[t];
                    int px = w & 0xFFFF, py = w >> 16;
                    int dx0 = x0[j] - px, dy0 = y0[j] - py;
                    bool cx0 = (unsigned)(dx0 + R_)     <= 2u * R_;
                    bool cx1 = (unsigned)(dx0 + R_ + 1) <= 2u * R_;
                    bool cy0 = (unsigned)(dy0 + R_)     <= 2u * R_;
                    bool cy1 = (unsigned)(dy0 + R_ + 1) <= 2u * R_;
                    int k00 = dx0 * dx0 + dy0 * dy0;
                    int k01 = k00 + 2 * dx0 + 1;
                    int k10 = k00 + 2 * dy0 + 1;
                    int k11 = k01 + 2 * dy0 + 1;
                    if (cx0 && cy0) m[j][0] = min(m[j][0], k00);
                    if (cx1 && cy0) m[j][1] = min(m[j][1], k01);
                    if (cx0 && cy1) m[j][2] = min(m[j][2], k10);
                    if (cx1 && cy1) m[j][3] = min(m[j][3], k11);
                }
            }
        }
        #pragma unroll
        for (int j = 0; j < 2; j++)
            #pragma unroll
            for (int cc = 0; cc < 4; cc++)
                m[j][cc] = (int)__reduce_min_sync(0xffffffffu, (unsigned)m[j][cc]);

        // lane-parallel epilogue: lane 4j+c -> query j, corner c (lanes 0-7)
        {
            int jj = (lane >> 2) & 1, cc = lane & 3;
            int mv = (jj == 0)
                ? ((cc == 0) ? m[0][0] : (cc == 1) ? m[0][1] : (cc == 2) ? m[0][2] : m[0][3])
                : ((cc == 0) ? m[1][0] : (cc == 1) ? m[1][1] : (cc == 2) ? m[1][2] : m[1][3]);
            float wxs = jj ? wx[1] : wx[0];
            float wys = jj ? wy[1] : wy[0];
            float fwx = (cc & 1) ? wxs : 1.f - wxs;
            float fwy = (cc & 2) ? wys : 1.f - wys;

            const float inv = 1.0f / (2.0f * 15.0f * 15.0f);
            float v = __expf(-(float)mv * inv);       // INT_MAX underflows to 0
            float term = v * fwx * fwy;
            term += __shfl_xor_sync(0xffffffffu, term, 1);
            term += __shfl_xor_sync(0xffffffffu, term, 2);
            float om  = 1.f - term;
            float raw = -om * om * __logf(fmaxf(term, 1e-6f));
            raw += __shfl_xor_sync(0xffffffffu, raw, 4);
            if (lane == 0) sm[warp] = raw;
        }
        __syncthreads();
        if (warp == 0) {
            float v = (lane < 8) ? sm[lane] : 0.f;
            v = warp_sum(v);
            if (lane == 0)     // deterministic: quantize block partial, integer add
                atomicAdd(&g_acc_pts, (unsigned long long)(long long)llrintf(v * FXS));
        }
    } else {
        // ====== CE: weighted cross-entropy, one block per 512-query slice ======
        const int cb = bid - PTS_BLOCKS;
        const int b  = cb >> 3;
        const int s  = cb & 7;

        float4 l = ((const float4*)(logits + (size_t)b * Q_ * 2 + s * 1024))[tid];
        int i0 = sidx[b * P_ + tid];
        int i1 = sidx[b * P_ + 256 + tid];

        if (tid < Q_ / 32) bm[tid] = 0u;
        __syncthreads();
        atomicOr(&bm[i0 >> 5], 1u << (i0 & 31));
        atomicOr(&bm[i1 >> 5], 1u << (i1 & 31));
        __syncthreads();

        int q0 = s * 512 + 2 * tid, q1 = q0 + 1;
        bool f0 = (bm[q0 >> 5] >> (q0 & 31)) & 1u;
        bool f1 = (bm[q1 >> 5] >> (q1 & 31)) & 1u;
        float d0 = l.y - l.x, d1 = l.w - l.z;
        float sp0 = fmaxf(d0, 0.f) + __logf(1.f + __expf(-fabsf(d0)));
        float sp1 = fmaxf(d1, 0.f) + __logf(1.f + __expf(-fabsf(d1)));
        float num = (f0 ? sp0 - d0 : 0.5f * sp0)
                  + (f1 ? sp1 - d1 : 0.5f * sp1);
        int   k   = (int)f0 + (int)f1;

        num = warp_sum(num);
        k   = __reduce_add_sync(0xffffffffu, (unsigned)k);
        if (lane == 0) { sm[warp] = num; smi[warp] = k; }
        __syncthreads();
        if (warp == 0) {
            float n = (lane < 8) ? sm[lane]  : 0.f;
            int   kk = (lane < 8) ? smi[lane] : 0;
            n  = warp_sum(n);
            kk = __reduce_add_sync(0xffffffffu, (unsigned)kk);
            if (lane == 0) {
                atomicAdd(&g_acc_num, (unsigned long long)(long long)llrintf(n * FXS));
                atomicAdd(&g_acc_k,   (unsigned long long)kk);
            }
        }
    }

    // ---------------- last-block-done: O(1) finalize ----------------
    __syncthreads();
    if (tid == 0) {
        __threadfence();
        unsigned int prev = atomicAdd(&g_done, 1u);
        s_last = (prev == (unsigned)(TOTAL_BLOCKS - 1)) ? 1 : 0;
    }
    __syncthreads();
    if (s_last && tid == 0) {
        __threadfence();
        unsigned long long ap = *(volatile unsigned long long*)&g_acc_pts;
        unsigned long long an = *(volatile unsigned long long*)&g_acc_num;
        unsigned long long ak = *(volatile unsigned long long*)&g_acc_k;

        float ptsSum = (float)((double)(long long)ap / (double)FXS);
        float ceN    = (float)((double)(long long)an / (double)FXS);
        float ceD    = 0.5f * (float)(B_ * Q_) + 0.5f * (float)ak;

        out[0] = ceN / ceD + 0.5f * ptsSum / (float)N_;

        // reset accumulators for next graph replay
        g_acc_pts = 0ull;
        g_acc_num = 0ull;
        g_acc_k   = 0ull;
        g_done    = 0u;
    }
}

extern "C" void kernel_launch(void* const* d_in, const int* in_sizes, int n_in,
                              void* d_out, int out_size) {
    const float* tp     = (const float*)d_in[0];
    const float* sp     = (const float*)d_in[1];
    const float* logits = (const float*)d_in[2];
    const int*   sidx   = (const int*)  d_in[4];

    k_fused<<<TOTAL_BLOCKS, THREADS_>>>(tp, sp, logits, sidx, (float*)d_out);
}